// round 2
// baseline (speedup 1.0000x reference)
#include <cuda_runtime.h>
#include <math.h>

#define BB 8
#define NN 2048
#define HH 256
#define MM (BB*NN)
#define KNB 6
#define INFD 1e9f

// ---------------- device scratch (no allocations allowed) ----------------
__device__ float g_agg[MM*HH];     // 16 MB: neighbor-aggregated features
__device__ float g_h1[MM*HH];      // 16 MB: layer-1 output
__device__ float g_norm[MM];       // row norms of h0
__device__ int   g_nbr[MM*KNB];    // neighbor indices (within batch)
__device__ float g_dist[MM*KNB];   // neighbor distances (INFD if invalid)
__device__ float g_w[MM*KNB];      // final edge weights

// ---------------- row norms of h0 ----------------
__global__ void __launch_bounds__(256) norm_kernel(const float* __restrict__ h) {
    int warp = threadIdx.x >> 5, lane = threadIdx.x & 31;
    int row = blockIdx.x * 8 + warp;
    const float4* p = (const float4*)(h + (size_t)row * HH);
    float4 a = p[lane * 2], b = p[lane * 2 + 1];
    float s = a.x*a.x + a.y*a.y + a.z*a.z + a.w*a.w
            + b.x*b.x + b.y*b.y + b.z*b.z + b.w*b.w;
    #pragma unroll
    for (int o = 16; o; o >>= 1) s += __shfl_xor_sync(0xffffffffu, s, o);
    if (lane == 0) g_norm[row] = sqrtf(s);
}

// ---------------- brute-force kNN (top-6) ----------------
// Rank by EXACT reference quantity: d2 = rn(dx*dx) + rn(dy*dy), contraction
// suppressed, so ordering == reference's dist ordering (sqrt monotone).
// Final merge sorts by (sqrtf(d2), idx) to match top_k tie-break semantics.
__global__ void __launch_bounds__(256) knn_kernel(const float* __restrict__ cent,
                                                  const unsigned char* __restrict__ pad) {
    __shared__ float2 tbl[NN];          // centroid table; padded -> (1e30,1e30)
    __shared__ float  mk[32 * 64];
    __shared__ int    mi[32 * 64];

    int b = blockIdx.y;
    int tid = threadIdx.x;
    const float* cb = cent + (size_t)b * NN * 2;
    for (int j = tid; j < NN; j += 256) {
        float cx = cb[2 * j], cy = cb[2 * j + 1];
        if (pad[b * NN + j]) { cx = 1e30f; cy = 1e30f; }
        tbl[j] = make_float2(cx, cy);
    }
    __syncthreads();

    int g = tid >> 3, sub = tid & 7;
    int q = blockIdx.x * 32 + g;
    float2 qc = tbl[q];

    // per-subthread top-8 by exact d2 (self + 6 + spare for sqrt ties)
    float bk[8]; int bi[8];
    #pragma unroll
    for (int t = 0; t < 8; t++) { bk[t] = 3.0e38f; bi[t] = 0x7fffffff; }

    #pragma unroll 4
    for (int it = 0; it < NN / 8; ++it) {
        int j = it * 8 + sub;
        float2 c = tbl[j];
        float dx = __fadd_rn(qc.x, -c.x);
        float dy = __fadd_rn(qc.y, -c.y);
        float key = __fadd_rn(__fmul_rn(dx, dx), __fmul_rn(dy, dy));
        if (key < bk[7]) {
            bk[7] = key; bi[7] = j;
            #pragma unroll
            for (int t = 7; t > 0; --t) {
                if (bk[t] < bk[t - 1]) {     // ascending j per subthread -> stable
                    float tk = bk[t]; bk[t] = bk[t - 1]; bk[t - 1] = tk;
                    int   ti = bi[t]; bi[t] = bi[t - 1]; bi[t - 1] = ti;
                }
            }
        }
    }

    #pragma unroll
    for (int t = 0; t < 8; t++) {
        mk[g * 64 + sub * 8 + t] = bk[t];
        mi[g * 64 + sub * 8 + t] = bi[t];
    }
    __syncwarp();

    if (sub == 0) {
        // merge 64 -> top-7 by (sqrt(d2), idx) lexicographic (reference order)
        float fs[7]; int fi[7];
        #pragma unroll
        for (int t = 0; t < 7; t++) { fs[t] = 3.0e38f; fi[t] = 0x7fffffff; }
        for (int e = 0; e < 64; ++e) {
            float k2 = mk[g * 64 + e];
            int   i  = mi[g * 64 + e];
            float s  = sqrtf(fmaxf(k2, 0.f));          // reference dist
            bool better = (s < fs[6]) || (s == fs[6] && i < fi[6]);
            if (better) {
                fs[6] = s; fi[6] = i;
                #pragma unroll
                for (int t = 6; t > 0; --t) {
                    bool sw = (fs[t] < fs[t - 1]) || (fs[t] == fs[t - 1] && fi[t] < fi[t - 1]);
                    if (sw) {
                        float tk = fs[t]; fs[t] = fs[t - 1]; fs[t - 1] = tk;
                        int   ti = fi[t]; fi[t] = fi[t - 1]; fi[t - 1] = ti;
                    }
                }
            }
        }
        // drop self, emit 6 neighbors
        int row = b * NN + q;
        int outk = 0;
        bool skipped = false;
        for (int t = 0; t < 7 && outk < KNB; ++t) {
            if (!skipped && fi[t] == q) { skipped = true; continue; }
            int idx = fi[t];
            float dd = fs[t];
            if (dd >= 5e8f || idx >= NN) { dd = INFD; idx = 0; }  // sentinel/invalid
            g_nbr[row * KNB + outk]  = idx;
            g_dist[row * KNB + outk] = dd;
            outk++;
        }
        // if self never appeared (padded query), fill remaining slot
        for (; outk < KNB; ++outk) {
            g_nbr[row * KNB + outk] = 0;
            g_dist[row * KNB + outk] = INFD;
        }
    }
}

// ---------------- edge weights (spatial + semantic + cross-time) ----------------
__global__ void __launch_bounds__(256) weight_kernel(const float* __restrict__ h,
                                                     const unsigned char* __restrict__ pad,
                                                     const int* __restrict__ tids) {
    int warp = threadIdx.x >> 5, lane = threadIdx.x & 31;
    int row = blockIdx.x * 8 + warp;
    int b = row / NN;

    const float4* hp = (const float4*)(h + (size_t)row * HH);
    float4 qa = hp[lane * 2], qb = hp[lane * 2 + 1];
    float nq = fmaxf(g_norm[row], 1e-12f);

    float invd[6], sim[6]; int nb[6]; bool val[6];
    float sum_inv = 0.f, sum_sim = 0.f;
    #pragma unroll
    for (int k = 0; k < KNB; k++) {
        int idx  = g_nbr[row * KNB + k];
        float dk = g_dist[row * KNB + k];
        int nrow = b * NN + idx;
        const float4* np = (const float4*)(h + (size_t)nrow * HH);
        float4 na = np[lane * 2], nb4 = np[lane * 2 + 1];
        float dot = qa.x*na.x + qa.y*na.y + qa.z*na.z + qa.w*na.w
                  + qb.x*nb4.x + qb.y*nb4.y + qb.z*nb4.z + qb.w*nb4.w;
        #pragma unroll
        for (int o = 16; o; o >>= 1) dot += __shfl_xor_sync(0xffffffffu, dot, o);
        float nn = fmaxf(g_norm[nrow], 1e-12f);
        bool v = dk < 5e8f;
        float s  = v ? fmaxf(dot / (nq * nn), 0.f) : 0.f;
        float id = v ? (1.f / fmaxf(dk, 1e-4f)) : 0.f;
        invd[k] = id; sim[k] = s; nb[k] = idx; val[k] = v;
        sum_inv += id; sum_sim += s;
    }

    if (lane == 0) {
        bool pq = pad[row] != 0;
        int tq = tids[row];
        float rs = 1.f / fmaxf(sum_inv, 1e-8f);
        float rm = 1.f / fmaxf(sum_sim, 1e-8f);
        float w[6]; float tot = 0.f;
        #pragma unroll
        for (int k = 0; k < KNB; k++) {
            float wk = 0.6f * invd[k] * rs + 0.4f * sim[k] * rm;
            int tnb = tids[b * NN + nb[k]];
            if (val[k] && (tq != tnb)) wk *= 1.2f;
            w[k] = wk; tot += wk;
        }
        float rt = 1.f / fmaxf(tot, 1e-8f);
        #pragma unroll
        for (int k = 0; k < KNB; k++)
            g_w[row * KNB + k] = pq ? 0.f : w[k] * rt;
    }
}

// ---------------- neighbor aggregation ----------------
__global__ void __launch_bounds__(256) agg_kernel(const float* __restrict__ h) {
    int row = blockIdx.x;
    int b = row >> 11;
    __shared__ float sw[KNB];
    __shared__ int   si[KNB];
    int t = threadIdx.x;
    if (t < KNB) { sw[t] = g_w[row * KNB + t]; si[t] = g_nbr[row * KNB + t]; }
    __syncthreads();
    float a = 0.f;
    #pragma unroll
    for (int k = 0; k < KNB; k++)
        a = fmaf(sw[k], h[((size_t)(b * NN + si[k])) * HH + t], a);
    g_agg[(size_t)row * HH + t] = a;
}

// ---------------- fused GEMM + GELU + LayerNorm + residual ----------------
// C[m,o] = sum_{k<256} hin[m,k]*Ws[o,k] + sum_{k<256} agg[m,k]*Wn[o,k]
// BM=64, BN=256, BK=16; 256 threads; each warp owns 8 full rows -> LN via shuffles.
__global__ void __launch_bounds__(256, 2) gemm_ln_kernel(
    const float* __restrict__ hin,
    const float* __restrict__ Ws, const float* __restrict__ Wn,
    const float* __restrict__ gv, const float* __restrict__ bvv,
    const unsigned char* __restrict__ pad,
    float* __restrict__ hout, int zero_pad)
{
    __shared__ float As[16][68];
    __shared__ float Bs[16][260];

    int tid = threadIdx.x;
    int m0 = blockIdx.x * 64;
    int ty = tid >> 5, tx = tid & 31;

    float acc[8][8];
    #pragma unroll
    for (int i = 0; i < 8; i++)
        #pragma unroll
        for (int j = 0; j < 8; j++) acc[i][j] = 0.f;

    int lr = tid >> 2;           // 0..63
    int lc = (tid & 3) * 4;      // 0,4,8,12

    for (int k0 = 0; k0 < 512; k0 += 16) {
        const float* Asrc = (k0 < 256)
            ? (hin   + (size_t)(m0 + lr) * HH + k0 + lc)
            : (g_agg + (size_t)(m0 + lr) * HH + (k0 - 256) + lc);
        float4 av = *(const float4*)Asrc;
        As[lc + 0][lr] = av.x; As[lc + 1][lr] = av.y;
        As[lc + 2][lr] = av.z; As[lc + 3][lr] = av.w;

        const float* Bsrc = (k0 < 256) ? (Ws + k0) : (Wn + (k0 - 256));
        #pragma unroll
        for (int i = 0; i < 4; i++) {
            int o = lr + 64 * i;
            float4 bv4 = *(const float4*)(Bsrc + (size_t)o * HH + lc);
            Bs[lc + 0][o] = bv4.x; Bs[lc + 1][o] = bv4.y;
            Bs[lc + 2][o] = bv4.z; Bs[lc + 3][o] = bv4.w;
        }
        __syncthreads();

        #pragma unroll
        for (int k = 0; k < 16; k++) {
            float4 a0 = *(const float4*)&As[k][ty * 8];
            float4 a1 = *(const float4*)&As[k][ty * 8 + 4];
            float4 b0 = *(const float4*)&Bs[k][tx * 8];
            float4 b1 = *(const float4*)&Bs[k][tx * 8 + 4];
            float a[8] = {a0.x, a0.y, a0.z, a0.w, a1.x, a1.y, a1.z, a1.w};
            float bb[8] = {b0.x, b0.y, b0.z, b0.w, b1.x, b1.y, b1.z, b1.w};
            #pragma unroll
            for (int i = 0; i < 8; i++)
                #pragma unroll
                for (int j = 0; j < 8; j++)
                    acc[i][j] = fmaf(a[i], bb[j], acc[i][j]);
        }
        __syncthreads();
    }

    // epilogue: gelu -> LN (per full row via warp reduce) -> residual
    float4 g0 = *(const float4*)(gv + tx * 8);
    float4 g1 = *(const float4*)(gv + tx * 8 + 4);
    float4 bb0 = *(const float4*)(bvv + tx * 8);
    float4 bb1 = *(const float4*)(bvv + tx * 8 + 4);
    float gr[8] = {g0.x, g0.y, g0.z, g0.w, g1.x, g1.y, g1.z, g1.w};
    float br[8] = {bb0.x, bb0.y, bb0.z, bb0.w, bb1.x, bb1.y, bb1.z, bb1.w};

    #pragma unroll
    for (int r = 0; r < 8; r++) {
        int row = m0 + ty * 8 + r;
        float v[8]; float s = 0.f, s2 = 0.f;
        #pragma unroll
        for (int j = 0; j < 8; j++) {
            float x = acc[r][j];
            float gl = 0.5f * x * (1.0f + erff(x * 0.70710678118654752f));
            v[j] = gl; s += gl; s2 = fmaf(gl, gl, s2);
        }
        #pragma unroll
        for (int o = 16; o; o >>= 1) {
            s  += __shfl_xor_sync(0xffffffffu, s, o);
            s2 += __shfl_xor_sync(0xffffffffu, s2, o);
        }
        float mu = s * (1.f / HH);
        float var = fmaf(-mu, mu, s2 * (1.f / HH));
        float rstd = rsqrtf(var + 1e-5f);

        bool pz = (zero_pad != 0) && (pad[row] != 0);
        const float* hp = hin + (size_t)row * HH + tx * 8;
        float4 h0v = *(const float4*)hp;
        float4 h1v = *(const float4*)(hp + 4);
        float hv[8] = {h0v.x, h0v.y, h0v.z, h0v.w, h1v.x, h1v.y, h1v.z, h1v.w};

        float o_[8];
        #pragma unroll
        for (int j = 0; j < 8; j++)
            o_[j] = pz ? 0.f : hv[j] + (v[j] - mu) * rstd * gr[j] + br[j];

        float4 w0 = make_float4(o_[0], o_[1], o_[2], o_[3]);
        float4 w1 = make_float4(o_[4], o_[5], o_[6], o_[7]);
        float* op = hout + (size_t)row * HH + tx * 8;
        *(float4*)op = w0;
        *(float4*)(op + 4) = w1;
    }
}

// ---------------- launcher ----------------
extern "C" void kernel_launch(void* const* d_in, const int* in_sizes, int n_in,
                              void* d_out, int out_size) {
    const float*         h0   = (const float*)d_in[0];
    const unsigned char* pad  = (const unsigned char*)d_in[1];
    const float*         cent = (const float*)d_in[2];
    const int*           tids = (const int*)d_in[3];
    const float* Ws1 = (const float*)d_in[4];
    const float* Wn1 = (const float*)d_in[5];
    const float* g1  = (const float*)d_in[6];
    const float* b1  = (const float*)d_in[7];
    const float* Ws2 = (const float*)d_in[8];
    const float* Wn2 = (const float*)d_in[9];
    const float* g2  = (const float*)d_in[10];
    const float* b2  = (const float*)d_in[11];
    float* out = (float*)d_out;

    float* h1;
    cudaGetSymbolAddress((void**)&h1, g_h1);

    norm_kernel  <<<MM / 8, 256>>>(h0);
    knn_kernel   <<<dim3(NN / 32, BB), 256>>>(cent, pad);
    weight_kernel<<<MM / 8, 256>>>(h0, pad, tids);

    agg_kernel   <<<MM, 256>>>(h0);
    gemm_ln_kernel<<<MM / 64, 256>>>(h0, Ws1, Wn1, g1, b1, pad, h1, 0);

    agg_kernel   <<<MM, 256>>>(h1);
    gemm_ln_kernel<<<MM / 64, 256>>>(h1, Ws2, Wn2, g2, b2, pad, out, 1);
}

// round 5
// speedup vs baseline: 1.2178x; 1.2178x over previous
#include <cuda_runtime.h>
#include <math.h>
#include <stdint.h>

#define BB 8
#define NN 2048
#define HH 256
#define MM (BB*NN)
#define KNB 6
#define INFD 1e9f

// ---------------- device scratch ----------------
__device__ float g_h1[MM*HH];          // layer-1 output
__device__ float g_norm[MM];
__device__ int   g_nbr[MM*KNB];
__device__ float g_dist[MM*KNB];
__device__ float g_w[MM*KNB];
__device__ float g_whi[2*256*512];     // tf32-hi of [Ws;Wn] per layer, [n][kk]
__device__ float g_wlo[2*256*512];     // tf32-lo

// ---------------- helpers ----------------
__device__ __forceinline__ uint32_t smem_u32(const void* p) {
    uint32_t a;
    asm("{ .reg .u64 t; cvta.to.shared.u64 t, %1; cvt.u32.u64 %0, t; }" : "=r"(a) : "l"(p));
    return a;
}
// tf32 destination is a .b32 container register (NOT .f32)
__device__ __forceinline__ uint32_t tf32r(float x) {
    uint32_t r; asm("cvt.rna.tf32.f32 %0, %1;" : "=r"(r) : "f"(x)); return r;
}
__device__ __forceinline__ float tf32f(float x) {
    return __uint_as_float(tf32r(x));
}
__device__ __forceinline__ void mma8(float* c, uint32_t a0, uint32_t a1,
                                     uint32_t a2, uint32_t a3,
                                     uint32_t b0, uint32_t b1) {
    asm volatile("mma.sync.aligned.m16n8k8.row.col.f32.tf32.tf32.f32 "
                 "{%0,%1,%2,%3}, {%4,%5,%6,%7}, {%8,%9}, {%0,%1,%2,%3};"
                 : "+f"(c[0]), "+f"(c[1]), "+f"(c[2]), "+f"(c[3])
                 : "r"(a0), "r"(a1), "r"(a2), "r"(a3), "r"(b0), "r"(b1));
}
__device__ __forceinline__ void cp16(uint32_t dst, const void* src) {
    asm volatile("cp.async.ca.shared.global [%0], [%1], 16;" :: "r"(dst), "l"(src) : "memory");
}

// ---------------- SMEM layout for gemm (bytes) ----------------
#define PADK 36
#define OFF_AHI  0
#define OFF_ALO  9216
#define OFF_BHI  18432
#define OFF_BLO  55296
#define OFF_SI   92160
#define OFF_SW   93696
#define OFF_R1   95232
#define OFF_R2   96256
#define OFF_GAM  97280
#define OFF_BET  98304
#define SMEM_TOTAL 99328

// ---------------- row norms ----------------
__global__ void __launch_bounds__(256) norm_kernel(const float* __restrict__ h) {
    int warp = threadIdx.x >> 5, lane = threadIdx.x & 31;
    int row = blockIdx.x * 8 + warp;
    const float4* p = (const float4*)(h + (size_t)row * HH);
    float4 a = p[lane * 2], b = p[lane * 2 + 1];
    float s = a.x*a.x + a.y*a.y + a.z*a.z + a.w*a.w
            + b.x*b.x + b.y*b.y + b.z*b.z + b.w*b.w;
    #pragma unroll
    for (int o = 16; o; o >>= 1) s += __shfl_xor_sync(0xffffffffu, s, o);
    if (lane == 0) g_norm[row] = sqrtf(s);
}

// ---------------- brute-force kNN (top-6), exact reference ordering ----------------
__global__ void __launch_bounds__(256) knn_kernel(const float* __restrict__ cent,
                                                  const unsigned char* __restrict__ pad) {
    __shared__ float2 tbl[NN];
    __shared__ float  mk[32 * 64];
    __shared__ int    mi[32 * 64];

    int b = blockIdx.y;
    int tid = threadIdx.x;
    const float* cb = cent + (size_t)b * NN * 2;
    for (int j = tid; j < NN; j += 256) {
        float cx = cb[2 * j], cy = cb[2 * j + 1];
        if (pad[b * NN + j]) { cx = 1e30f; cy = 1e30f; }
        tbl[j] = make_float2(cx, cy);
    }
    __syncthreads();

    int g = tid >> 3, sub = tid & 7;
    int q = blockIdx.x * 32 + g;
    float2 qc = tbl[q];

    float bk[8]; int bi[8];
    #pragma unroll
    for (int t = 0; t < 8; t++) { bk[t] = 3.0e38f; bi[t] = 0x7fffffff; }

    #pragma unroll 4
    for (int it = 0; it < NN / 8; ++it) {
        int j = it * 8 + sub;
        float2 c = tbl[j];
        float dx = __fadd_rn(qc.x, -c.x);
        float dy = __fadd_rn(qc.y, -c.y);
        float key = __fadd_rn(__fmul_rn(dx, dx), __fmul_rn(dy, dy));
        if (key < bk[7]) {
            bk[7] = key; bi[7] = j;
            #pragma unroll
            for (int t = 7; t > 0; --t) {
                if (bk[t] < bk[t - 1]) {
                    float tk = bk[t]; bk[t] = bk[t - 1]; bk[t - 1] = tk;
                    int   ti = bi[t]; bi[t] = bi[t - 1]; bi[t - 1] = ti;
                }
            }
        }
    }

    #pragma unroll
    for (int t = 0; t < 8; t++) {
        mk[g * 64 + sub * 8 + t] = bk[t];
        mi[g * 64 + sub * 8 + t] = bi[t];
    }
    __syncwarp();

    if (sub == 0) {
        float fs[7]; int fi[7];
        #pragma unroll
        for (int t = 0; t < 7; t++) { fs[t] = 3.0e38f; fi[t] = 0x7fffffff; }
        for (int e = 0; e < 64; ++e) {
            float k2 = mk[g * 64 + e];
            int   i  = mi[g * 64 + e];
            float s  = sqrtf(fmaxf(k2, 0.f));
            bool better = (s < fs[6]) || (s == fs[6] && i < fi[6]);
            if (better) {
                fs[6] = s; fi[6] = i;
                #pragma unroll
                for (int t = 6; t > 0; --t) {
                    bool sw = (fs[t] < fs[t - 1]) || (fs[t] == fs[t - 1] && fi[t] < fi[t - 1]);
                    if (sw) {
                        float tk = fs[t]; fs[t] = fs[t - 1]; fs[t - 1] = tk;
                        int   ti = fi[t]; fi[t] = fi[t - 1]; fi[t - 1] = ti;
                    }
                }
            }
        }
        int row = b * NN + q;
        int outk = 0;
        bool skipped = false;
        for (int t = 0; t < 7 && outk < KNB; ++t) {
            if (!skipped && fi[t] == q) { skipped = true; continue; }
            int idx = fi[t];
            float dd = fs[t];
            if (dd >= 5e8f || idx >= NN) { dd = INFD; idx = 0; }
            g_nbr[row * KNB + outk]  = idx;
            g_dist[row * KNB + outk] = dd;
            outk++;
        }
        for (; outk < KNB; ++outk) {
            g_nbr[row * KNB + outk] = 0;
            g_dist[row * KNB + outk] = INFD;
        }
    }
}

// ---------------- edge weights ----------------
__global__ void __launch_bounds__(256) weight_kernel(const float* __restrict__ h,
                                                     const unsigned char* __restrict__ pad,
                                                     const int* __restrict__ tids,
                                                     int rbase) {
    int warp = threadIdx.x >> 5, lane = threadIdx.x & 31;
    int row = rbase + blockIdx.x * 8 + warp;
    int b = row / NN;

    const float4* hp = (const float4*)(h + (size_t)row * HH);
    float4 qa = hp[lane * 2], qb = hp[lane * 2 + 1];
    float nq = fmaxf(g_norm[row], 1e-12f);

    float invd[6], sim[6]; int nb[6]; bool val[6];
    float sum_inv = 0.f, sum_sim = 0.f;
    #pragma unroll
    for (int k = 0; k < KNB; k++) {
        int idx  = g_nbr[row * KNB + k];
        float dk = g_dist[row * KNB + k];
        int nrow = b * NN + idx;
        const float4* np = (const float4*)(h + (size_t)nrow * HH);
        float4 na = np[lane * 2], nb4 = np[lane * 2 + 1];
        float dot = qa.x*na.x + qa.y*na.y + qa.z*na.z + qa.w*na.w
                  + qb.x*nb4.x + qb.y*nb4.y + qb.z*nb4.z + qb.w*nb4.w;
        #pragma unroll
        for (int o = 16; o; o >>= 1) dot += __shfl_xor_sync(0xffffffffu, dot, o);
        float nn = fmaxf(g_norm[nrow], 1e-12f);
        bool v = dk < 5e8f;
        float s  = v ? fmaxf(dot / (nq * nn), 0.f) : 0.f;
        float id = v ? (1.f / fmaxf(dk, 1e-4f)) : 0.f;
        invd[k] = id; sim[k] = s; nb[k] = idx; val[k] = v;
        sum_inv += id; sum_sim += s;
    }

    if (lane == 0) {
        bool pq = pad[row] != 0;
        int tq = tids[row];
        float rs = 1.f / fmaxf(sum_inv, 1e-8f);
        float rm = 1.f / fmaxf(sum_sim, 1e-8f);
        float w[6]; float tot = 0.f;
        #pragma unroll
        for (int k = 0; k < KNB; k++) {
            float wk = 0.6f * invd[k] * rs + 0.4f * sim[k] * rm;
            int tnb = tids[b * NN + nb[k]];
            if (val[k] && (tq != tnb)) wk *= 1.2f;
            w[k] = wk; tot += wk;
        }
        float rt = 1.f / fmaxf(tot, 1e-8f);
        #pragma unroll
        for (int k = 0; k < KNB; k++)
            g_w[row * KNB + k] = pq ? 0.f : w[k] * rt;
    }
}

// ---------------- weight tf32 hi/lo pre-split: g_whi/g_wlo[L][n][kk] ----------------
__global__ void __launch_bounds__(256) wsplit_kernel(const float* __restrict__ Ws1,
                                                     const float* __restrict__ Wn1,
                                                     const float* __restrict__ Ws2,
                                                     const float* __restrict__ Wn2) {
    int idx = blockIdx.x * 256 + threadIdx.x;       // 0 .. 262143
    int L   = idx >> 17;
    int rem = idx & 131071;
    int n   = rem >> 9;
    int kk  = rem & 511;
    const float* W = (L == 0) ? (kk < 256 ? Ws1 : Wn1) : (kk < 256 ? Ws2 : Wn2);
    float v = W[n * 256 + (kk & 255)];
    float hi = tf32f(v);
    g_whi[idx] = hi;
    g_wlo[idx] = tf32f(v - hi);
}

// ---------------- fused tf32x3 mma.sync GEMM + gather-agg + GELU + LN + residual ----------------
// CTA: 64 rows x 256 cols, K=512 (hin k<256; fused agg k>=256). 8 warps = 2(M) x 4(N).
__global__ void __launch_bounds__(256, 2) gemm_ln_mma(
    const float* __restrict__ hin, int L,
    const float* __restrict__ gv, const float* __restrict__ bv,
    const unsigned char* __restrict__ pad,
    float* __restrict__ hout, int zero_pad)
{
    extern __shared__ char sm[];
    float* As_hi = (float*)(sm + OFF_AHI);
    float* As_lo = (float*)(sm + OFF_ALO);
    float* Bs_hi = (float*)(sm + OFF_BHI);
    float* Bs_lo = (float*)(sm + OFF_BLO);
    int*   si    = (int*)(sm + OFF_SI);
    float* sw    = (float*)(sm + OFF_SW);
    float* red1  = (float*)(sm + OFF_R1);
    float* red2  = (float*)(sm + OFF_R2);
    float* sgam  = (float*)(sm + OFF_GAM);
    float* sbet  = (float*)(sm + OFF_BET);
    uint32_t sb  = smem_u32(sm);

    int tid = threadIdx.x;
    int m0 = blockIdx.x * 64;
    int bbase = (m0 >> 11) * NN;
    int wid = tid >> 5, lane = tid & 31;
    int mw = wid >> 2, nw = wid & 3;       // warp grid 2 x 4
    int g = lane >> 2, i = lane & 3;

    // preload per-row gather metadata + gamma/beta
    for (int e = tid; e < 64 * KNB; e += 256) {
        int r = e / KNB, k = e % KNB;
        si[e] = g_nbr[(size_t)(m0 + r) * KNB + k];
        sw[e] = g_w[(size_t)(m0 + r) * KNB + k];
    }
    sgam[tid] = gv[tid];
    sbet[tid] = bv[tid];

    float acc[2][8][4];
    #pragma unroll
    for (int a = 0; a < 2; a++)
        #pragma unroll
        for (int b = 0; b < 8; b++)
            #pragma unroll
            for (int c = 0; c < 4; c++) acc[a][b][c] = 0.f;

    const float* gwh = g_whi + (size_t)L * 131072;
    const float* gwl = g_wlo + (size_t)L * 131072;

    for (int c = 0; c < 16; ++c) {
        __syncthreads();                 // previous chunk's LDS all done
        int k0 = (c & 7) * 32;

        // ---- B tiles via cp.async: 256 n-rows x 32 k, hi & lo ----
        #pragma unroll
        for (int t = 0; t < 8; ++t) {
            int fidx = t * 256 + tid;    // 0..2047
            int n = fidx >> 3, q4 = fidx & 7;
            uint32_t doff = (uint32_t)((n * PADK + q4 * 4) * 4);
            const float* srch = gwh + (size_t)n * 512 + c * 32 + q4 * 4;
            const float* srcl = gwl + (size_t)n * 512 + c * 32 + q4 * 4;
            cp16(sb + OFF_BHI + doff, srch);
            cp16(sb + OFF_BLO + doff, srcl);
        }
        asm volatile("cp.async.commit_group;" ::: "memory");

        // ---- A tile: 64 rows x 32 k, hi/lo (fused gather-agg for c>=8) ----
        #pragma unroll
        for (int t = 0; t < 2; ++t) {
            int fidx = tid * 2 + t;      // 0..511
            int r = fidx >> 3, q4 = fidx & 7;
            float4 v;
            if (c < 8) {
                v = *(const float4*)(hin + (size_t)(m0 + r) * HH + k0 + q4 * 4);
            } else {
                v = make_float4(0.f, 0.f, 0.f, 0.f);
                #pragma unroll
                for (int j = 0; j < KNB; ++j) {
                    float wj = sw[r * KNB + j];
                    const float4 nv = *(const float4*)(hin +
                        (size_t)(bbase + si[r * KNB + j]) * HH + k0 + q4 * 4);
                    v.x = fmaf(wj, nv.x, v.x);
                    v.y = fmaf(wj, nv.y, v.y);
                    v.z = fmaf(wj, nv.z, v.z);
                    v.w = fmaf(wj, nv.w, v.w);
                }
            }
            float4 hi, lo;
            hi.x = tf32f(v.x); lo.x = tf32f(v.x - hi.x);
            hi.y = tf32f(v.y); lo.y = tf32f(v.y - hi.y);
            hi.z = tf32f(v.z); lo.z = tf32f(v.z - hi.z);
            hi.w = tf32f(v.w); lo.w = tf32f(v.w - hi.w);
            int off = r * PADK + q4 * 4;
            *(float4*)(As_hi + off) = hi;
            *(float4*)(As_lo + off) = lo;
        }
        asm volatile("cp.async.wait_all;" ::: "memory");
        __syncthreads();

        // ---- MMA: 4 k8-steps ----
        #pragma unroll
        for (int k8 = 0; k8 < 4; ++k8) {
            int kc = k8 * 8 + i;
            uint32_t ah[2][4], al[2][4];
            #pragma unroll
            for (int fm = 0; fm < 2; ++fm) {
                const float* p = As_hi + (mw * 32 + fm * 16 + g) * PADK + kc;
                const float* q = As_lo + (mw * 32 + fm * 16 + g) * PADK + kc;
                ah[fm][0] = __float_as_uint(p[0]);
                ah[fm][1] = __float_as_uint(p[8 * PADK]);
                ah[fm][2] = __float_as_uint(p[4]);
                ah[fm][3] = __float_as_uint(p[8 * PADK + 4]);
                al[fm][0] = __float_as_uint(q[0]);
                al[fm][1] = __float_as_uint(q[8 * PADK]);
                al[fm][2] = __float_as_uint(q[4]);
                al[fm][3] = __float_as_uint(q[8 * PADK + 4]);
            }
            #pragma unroll
            for (int fn = 0; fn < 8; ++fn) {
                const float* pb = Bs_hi + (nw * 64 + fn * 8 + g) * PADK + kc;
                const float* ql = Bs_lo + (nw * 64 + fn * 8 + g) * PADK + kc;
                uint32_t bh0 = __float_as_uint(pb[0]);
                uint32_t bh1 = __float_as_uint(pb[4]);
                uint32_t bl0 = __float_as_uint(ql[0]);
                uint32_t bl1 = __float_as_uint(ql[4]);
                #pragma unroll
                for (int fm = 0; fm < 2; ++fm) {
                    mma8(acc[fm][fn], ah[fm][0], ah[fm][1], ah[fm][2], ah[fm][3], bh0, bh1);
                    mma8(acc[fm][fn], ah[fm][0], ah[fm][1], ah[fm][2], ah[fm][3], bl0, bl1);
                    mma8(acc[fm][fn], al[fm][0], al[fm][1], al[fm][2], al[fm][3], bh0, bh1);
                }
            }
        }
    }
    __syncthreads();

    // ---- epilogue: GELU -> LN stats -> normalize + residual + store ----
    float s1[4] = {0.f, 0.f, 0.f, 0.f};
    float s2[4] = {0.f, 0.f, 0.f, 0.f};
    #pragma unroll
    for (int fm = 0; fm < 2; ++fm)
        #pragma unroll
        for (int fn = 0; fn < 8; ++fn)
            #pragma unroll
            for (int cc = 0; cc < 4; ++cc) {
                float x = acc[fm][fn][cc];
                float gl = 0.5f * x * (1.0f + erff(x * 0.70710678118654752f));
                acc[fm][fn][cc] = gl;
                int rs = fm * 2 + (cc >> 1);
                s1[rs] += gl;
                s2[rs] = fmaf(gl, gl, s2[rs]);
            }
    #pragma unroll
    for (int rs = 0; rs < 4; ++rs) {
        #pragma unroll
        for (int o = 1; o <= 2; o <<= 1) {
            s1[rs] += __shfl_xor_sync(0xffffffffu, s1[rs], o);
            s2[rs] += __shfl_xor_sync(0xffffffffu, s2[rs], o);
        }
    }
    if (i == 0) {
        #pragma unroll
        for (int rs = 0; rs < 4; ++rs) {
            int row_l = mw * 32 + (rs >> 1) * 16 + g + (rs & 1) * 8;
            red1[row_l * 4 + nw] = s1[rs];
            red2[row_l * 4 + nw] = s2[rs];
        }
    }
    __syncthreads();

    #pragma unroll
    for (int fm = 0; fm < 2; ++fm) {
        #pragma unroll
        for (int rh = 0; rh < 2; ++rh) {
            int row_l = mw * 32 + fm * 16 + g + rh * 8;
            int row_g = m0 + row_l;
            float st  = red1[row_l * 4 + 0] + red1[row_l * 4 + 1]
                      + red1[row_l * 4 + 2] + red1[row_l * 4 + 3];
            float st2 = red2[row_l * 4 + 0] + red2[row_l * 4 + 1]
                      + red2[row_l * 4 + 2] + red2[row_l * 4 + 3];
            float mu   = st * (1.f / HH);
            float var  = fmaf(-mu, mu, st2 * (1.f / HH));
            float rstd = rsqrtf(var + 1e-5f);
            bool pz = (zero_pad != 0) && (pad[row_g] != 0);
            #pragma unroll
            for (int fn = 0; fn < 8; ++fn) {
                int col = nw * 64 + fn * 8 + 2 * i;
                float v0 = acc[fm][fn][rh * 2 + 0];
                float v1 = acc[fm][fn][rh * 2 + 1];
                float2 res = *(const float2*)(hin + (size_t)row_g * HH + col);
                float2 o;
                o.x = pz ? 0.f : res.x + (v0 - mu) * rstd * sgam[col]     + sbet[col];
                o.y = pz ? 0.f : res.y + (v1 - mu) * rstd * sgam[col + 1] + sbet[col + 1];
                *(float2*)(hout + (size_t)row_g * HH + col) = o;
            }
        }
    }
}

// ---------------- launcher ----------------
extern "C" void kernel_launch(void* const* d_in, const int* in_sizes, int n_in,
                              void* d_out, int out_size) {
    const float*         h0   = (const float*)d_in[0];
    const unsigned char* pad  = (const unsigned char*)d_in[1];
    const float*         cent = (const float*)d_in[2];
    const int*           tids = (const int*)d_in[3];
    const float* Ws1 = (const float*)d_in[4];
    const float* Wn1 = (const float*)d_in[5];
    const float* g1  = (const float*)d_in[6];
    const float* b1  = (const float*)d_in[7];
    const float* Ws2 = (const float*)d_in[8];
    const float* Wn2 = (const float*)d_in[9];
    const float* g2  = (const float*)d_in[10];
    const float* b2  = (const float*)d_in[11];
    float* out = (float*)d_out;

    float* h1;
    cudaGetSymbolAddress((void**)&h1, g_h1);

    cudaFuncSetAttribute(gemm_ln_mma, cudaFuncAttributeMaxDynamicSharedMemorySize, SMEM_TOTAL);

    norm_kernel  <<<MM / 8, 256>>>(h0);
    knn_kernel   <<<dim3(NN / 32, BB), 256>>>(cent, pad);
    weight_kernel<<<MM / 16, 256>>>(h0, pad, tids, 0);
    weight_kernel<<<MM / 16, 256>>>(h0, pad, tids, MM / 2);
    wsplit_kernel<<<1024, 256>>>(Ws1, Wn1, Ws2, Wn2);

    gemm_ln_mma<<<MM / 64, 256, SMEM_TOTAL>>>(h0, 0, g1, b1, pad, h1, 0);
    gemm_ln_mma<<<MM / 64, 256, SMEM_TOTAL>>>(h1, 1, g2, b2, pad, out, 1);
}